// round 1
// baseline (speedup 1.0000x reference)
#include <cuda_runtime.h>
#include <math.h>

// Problem constants
#define T_TOK 4096      // B*L tokens
#define D_DIM 1024
#define E_NUM 8
#define F_DIM 2048
#define F2    4096      // 2*F
#define CAP   4096      // max tokens per expert

// -------- scratch (device globals; no allocations allowed) --------
__device__ int   g_cnt[E_NUM];
__device__ int   g_tok[E_NUM * CAP];           // token id per (expert, slot)
__device__ int   g_t2e[T_TOK * 2];             // token -> entry index (e*CAP+slot)
__device__ float g_t2w[T_TOK * 2];             // token -> routing weight
__device__ float g_h[(size_t)E_NUM * CAP * F_DIM];  // activated hidden, 268 MB
__device__ float g_y[(size_t)E_NUM * CAP * D_DIM];  // per-entry expert output, 134 MB

// -------- kernel 0: reset counters --------
__global__ void zero_cnt_kernel() {
    if (threadIdx.x < E_NUM) g_cnt[threadIdx.x] = 0;
}

// -------- kernel 1: gating + top-2 routing --------
__global__ void gate_kernel(const float* __restrict__ x,
                            const float* __restrict__ gw) {
    int t = blockIdx.x;
    __shared__ float xs[D_DIM];
    __shared__ float gates[E_NUM];
    int tid = threadIdx.x;

    for (int i = tid; i < D_DIM; i += blockDim.x)
        xs[i] = x[(size_t)t * D_DIM + i];
    __syncthreads();

    // 8 warps; warp w computes gate logit for expert w
    int wid = tid >> 5, lane = tid & 31;
    float s = 0.f;
    for (int d = lane; d < D_DIM; d += 32)
        s += xs[d] * gw[d * E_NUM + wid];
    #pragma unroll
    for (int o = 16; o > 0; o >>= 1)
        s += __shfl_down_sync(0xffffffffu, s, o);
    if (lane == 0) gates[wid] = s;
    __syncthreads();

    if (tid == 0) {
        // top-2 (stable: lower index wins ties, matching jax.lax.top_k)
        int i0 = 0; float g0 = gates[0];
        #pragma unroll
        for (int e = 1; e < E_NUM; e++)
            if (gates[e] > g0) { g0 = gates[e]; i0 = e; }
        int i1 = -1; float g1 = -1e30f;
        #pragma unroll
        for (int e = 0; e < E_NUM; e++)
            if (e != i0 && gates[e] > g1) { g1 = gates[e]; i1 = e; }

        float ex = expf(g1 - g0);          // g1 <= g0, safe
        float w0 = 1.f / (1.f + ex);
        float w1 = ex / (1.f + ex);

        int s0 = atomicAdd(&g_cnt[i0], 1);
        int s1 = atomicAdd(&g_cnt[i1], 1);
        g_tok[i0 * CAP + s0] = t;
        g_tok[i1 * CAP + s1] = t;
        g_t2e[t * 2 + 0] = i0 * CAP + s0;
        g_t2e[t * 2 + 1] = i1 * CAP + s1;
        g_t2w[t * 2 + 0] = w0;
        g_t2w[t * 2 + 1] = w1;
    }
}

// -------- kernel 2: grouped GEMM1 (h = x @ W1^T + b1) fused with SwiGLU --------
// 128x128x8 fp32 tile, 256 threads, 8x8 thread micro-tile.
__global__ void __launch_bounds__(256) ffn1_kernel(
    const float* __restrict__ x,
    const float* __restrict__ w1,
    const float* __restrict__ b1) {
    int e = blockIdx.z;
    int cnt = g_cnt[e];
    int row0 = blockIdx.y * 128;
    if (row0 >= cnt) return;
    int c0 = blockIdx.x * 128;     // column within 2F

    __shared__ int   stok[128];
    __shared__ float As[8][128];
    __shared__ float Bs[8][128];

    int tid = threadIdx.x;
    if (tid < 128) {
        int r = row0 + tid;
        stok[tid] = (r < cnt) ? g_tok[e * CAP + r] : 0;
    }
    __syncthreads();

    int lm = tid >> 1;             // tile row this thread loads (A and B)
    int lp = (tid & 1) * 4;        // k sub-offset
    const float* xbase = x  + (size_t)stok[lm] * D_DIM + lp;
    const float* wbase = w1 + ((size_t)e * F2 + c0 + lm) * D_DIM + lp;

    int tx = tid & 15, ty = tid >> 4;
    float acc[8][8];
    #pragma unroll
    for (int i = 0; i < 8; i++)
        #pragma unroll
        for (int j = 0; j < 8; j++) acc[i][j] = 0.f;

    for (int k0 = 0; k0 < D_DIM; k0 += 8) {
        float4 av = *(const float4*)(xbase + k0);
        float4 bv = *(const float4*)(wbase + k0);
        __syncthreads();
        As[lp + 0][lm] = av.x; As[lp + 1][lm] = av.y;
        As[lp + 2][lm] = av.z; As[lp + 3][lm] = av.w;
        Bs[lp + 0][lm] = bv.x; Bs[lp + 1][lm] = bv.y;
        Bs[lp + 2][lm] = bv.z; Bs[lp + 3][lm] = bv.w;
        __syncthreads();
        #pragma unroll
        for (int k = 0; k < 8; k++) {
            float a[8], b[8];
            *(float4*)(a)     = *(const float4*)&As[k][ty * 8];
            *(float4*)(a + 4) = *(const float4*)&As[k][ty * 8 + 4];
            *(float4*)(b)     = *(const float4*)&Bs[k][tx * 8];
            *(float4*)(b + 4) = *(const float4*)&Bs[k][tx * 8 + 4];
            #pragma unroll
            for (int i = 0; i < 8; i++)
                #pragma unroll
                for (int j = 0; j < 8; j++)
                    acc[i][j] += a[i] * b[j];
        }
    }

    // epilogue: add bias, SwiGLU on (even, odd) channel pairs, store F-space
    int cbase = c0 + tx * 8;       // even, so pairs are complete per thread
    float bb[8];
    #pragma unroll
    for (int j = 0; j < 8; j++) bb[j] = b1[e * F2 + cbase + j];

    #pragma unroll
    for (int i = 0; i < 8; i++) {
        int r = row0 + ty * 8 + i;
        if (r >= cnt) break;
        float* hrow = g_h + ((size_t)e * CAP + r) * F_DIM + (cbase >> 1);
        #pragma unroll
        for (int p = 0; p < 4; p++) {
            float g = acc[i][2 * p]     + bb[2 * p];
            float v = acc[i][2 * p + 1] + bb[2 * p + 1];
            g = fminf(g, 9.0f);
            v = fmaxf(fminf(v, 9.0f), -9.0f);
            float sig = 1.f / (1.f + __expf(-1.702f * g));
            hrow[p] = g * sig * (v + 1.f);
        }
    }
}

// -------- kernel 3: grouped GEMM2 (y = h @ W2^T + b2) --------
__global__ void __launch_bounds__(256) ffn2_kernel(
    const float* __restrict__ w2,
    const float* __restrict__ b2) {
    int e = blockIdx.z;
    int cnt = g_cnt[e];
    int row0 = blockIdx.y * 128;
    if (row0 >= cnt) return;
    int d0 = blockIdx.x * 128;

    __shared__ float As[8][128];
    __shared__ float Bs[8][128];

    int tid = threadIdx.x;
    int lm = tid >> 1;
    int lp = (tid & 1) * 4;
    int arow = row0 + lm;
    if (arow >= cnt) arow = row0;  // pad rows re-read a valid row (discarded)
    const float* hbase = g_h + ((size_t)e * CAP + arow) * F_DIM + lp;
    const float* wbase = w2 + ((size_t)e * D_DIM + d0 + lm) * F_DIM + lp;

    int tx = tid & 15, ty = tid >> 4;
    float acc[8][8];
    #pragma unroll
    for (int i = 0; i < 8; i++)
        #pragma unroll
        for (int j = 0; j < 8; j++) acc[i][j] = 0.f;

    for (int k0 = 0; k0 < F_DIM; k0 += 8) {
        float4 av = *(const float4*)(hbase + k0);
        float4 bv = *(const float4*)(wbase + k0);
        __syncthreads();
        As[lp + 0][lm] = av.x; As[lp + 1][lm] = av.y;
        As[lp + 2][lm] = av.z; As[lp + 3][lm] = av.w;
        Bs[lp + 0][lm] = bv.x; Bs[lp + 1][lm] = bv.y;
        Bs[lp + 2][lm] = bv.z; Bs[lp + 3][lm] = bv.w;
        __syncthreads();
        #pragma unroll
        for (int k = 0; k < 8; k++) {
            float a[8], b[8];
            *(float4*)(a)     = *(const float4*)&As[k][ty * 8];
            *(float4*)(a + 4) = *(const float4*)&As[k][ty * 8 + 4];
            *(float4*)(b)     = *(const float4*)&Bs[k][tx * 8];
            *(float4*)(b + 4) = *(const float4*)&Bs[k][tx * 8 + 4];
            #pragma unroll
            for (int i = 0; i < 8; i++)
                #pragma unroll
                for (int j = 0; j < 8; j++)
                    acc[i][j] += a[i] * b[j];
        }
    }

    int dbase = d0 + tx * 8;
    float bb[8];
    #pragma unroll
    for (int j = 0; j < 8; j++) bb[j] = b2[e * D_DIM + dbase + j];

    #pragma unroll
    for (int i = 0; i < 8; i++) {
        int r = row0 + ty * 8 + i;
        if (r >= cnt) break;
        float* yrow = g_y + ((size_t)e * CAP + r) * D_DIM + dbase;
        #pragma unroll
        for (int j = 0; j < 8; j++)
            yrow[j] = acc[i][j] + bb[j];
    }
}

// -------- kernel 4: deterministic weighted combine --------
__global__ void combine_kernel(float* __restrict__ out) {
    int t = blockIdx.x;
    int   e0 = g_t2e[t * 2 + 0], e1 = g_t2e[t * 2 + 1];
    float w0 = g_t2w[t * 2 + 0], w1 = g_t2w[t * 2 + 1];
    const float* y0 = g_y + (size_t)e0 * D_DIM;
    const float* y1 = g_y + (size_t)e1 * D_DIM;
    float* o = out + (size_t)t * D_DIM;
    for (int d = threadIdx.x; d < D_DIM; d += blockDim.x)
        o[d] = w0 * y0[d] + w1 * y1[d];
}

extern "C" void kernel_launch(void* const* d_in, const int* in_sizes, int n_in,
                              void* d_out, int out_size) {
    const float* x  = (const float*)d_in[0];  // [2,2048,1024]
    const float* gw = (const float*)d_in[1];  // [1024,8]
    const float* w1 = (const float*)d_in[2];  // [8,4096,1024]
    const float* b1 = (const float*)d_in[3];  // [8,4096]
    const float* w2 = (const float*)d_in[4];  // [8,1024,2048]
    const float* b2 = (const float*)d_in[5];  // [8,1024]
    float* out = (float*)d_out;               // [2,2048,1024]

    zero_cnt_kernel<<<1, 32>>>();
    gate_kernel<<<T_TOK, 256>>>(x, gw);
    ffn1_kernel<<<dim3(F2 / 128, T_TOK / 128, E_NUM), 256>>>(x, w1, b1);
    ffn2_kernel<<<dim3(D_DIM / 128, T_TOK / 128, E_NUM), 256>>>(w2, b2);
    combine_kernel<<<T_TOK, 256>>>(out);
}

// round 5
// speedup vs baseline: 2.3063x; 2.3063x over previous
#include <cuda_runtime.h>
#include <cuda_bf16.h>
#include <math.h>
#include <stdint.h>

// Problem constants
#define T_TOK 4096
#define D_DIM 1024
#define E_NUM 8
#define F_DIM 2048
#define F2    4096
#define CAP   4096

// Tile config
#define BM 128
#define BN 128
#define BK 32          // bf16 k per stage
#define RSB 80         // smem row stride in bytes (40 bf16) -> conflict-free ldmatrix
#define ABYTES (128 * RSB)       // 10240 per matrix
#define STAGE  (4 * ABYTES)      // Ah, Al, Bh, Bl
#define SMEM_BYTES (2 * STAGE)   // 81920

// ---------------- scratch (device globals; no allocs allowed) ----------------
__device__ int   g_cnt[E_NUM];
__device__ int   g_tok[E_NUM * CAP];
__device__ int   g_t2e[T_TOK * 2];
__device__ float g_t2w[T_TOK * 2];
__device__ __nv_bfloat16 g_Hh[(size_t)E_NUM * CAP * F_DIM];  // 134 MB
__device__ __nv_bfloat16 g_Hl[(size_t)E_NUM * CAP * F_DIM];  // 134 MB
__device__ float g_y[(size_t)E_NUM * CAP * D_DIM];           // 134 MB

// ---------------- helpers ----------------
__device__ __forceinline__ uint32_t smem_u32(const void* p) {
    uint32_t a;
    asm("{ .reg .u64 t; cvta.to.shared.u64 t, %1; cvt.u32.u64 %0, t; }" : "=r"(a) : "l"(p));
    return a;
}
__device__ __forceinline__ void ldsm_x4(uint32_t& r0, uint32_t& r1, uint32_t& r2, uint32_t& r3,
                                        uint32_t addr) {
    asm volatile("ldmatrix.sync.aligned.m8n8.x4.shared.b16 {%0,%1,%2,%3}, [%4];"
                 : "=r"(r0), "=r"(r1), "=r"(r2), "=r"(r3) : "r"(addr));
}
__device__ __forceinline__ void mma_bf16(float* c,
                                         uint32_t a0, uint32_t a1, uint32_t a2, uint32_t a3,
                                         uint32_t b0, uint32_t b1) {
    asm volatile("mma.sync.aligned.m16n8k16.row.col.f32.bf16.bf16.f32 "
                 "{%0,%1,%2,%3}, {%4,%5,%6,%7}, {%8,%9}, {%0,%1,%2,%3};"
                 : "+f"(c[0]), "+f"(c[1]), "+f"(c[2]), "+f"(c[3])
                 : "r"(a0), "r"(a1), "r"(a2), "r"(a3), "r"(b0), "r"(b1));
}

// fp32x4 -> split bf16 hi/lo (4 bf16 = 8B each)
__device__ __forceinline__ void split_store(char* hp, char* lp, float4 v) {
    uint32_t h01, h23, l01, l23;
    asm("cvt.rn.bf16x2.f32 %0, %1, %2;" : "=r"(h01) : "f"(v.y), "f"(v.x));
    asm("cvt.rn.bf16x2.f32 %0, %1, %2;" : "=r"(h23) : "f"(v.w), "f"(v.z));
    float r0 = v.x - __uint_as_float(h01 << 16);
    float r1 = v.y - __uint_as_float(h01 & 0xFFFF0000u);
    float r2 = v.z - __uint_as_float(h23 << 16);
    float r3 = v.w - __uint_as_float(h23 & 0xFFFF0000u);
    asm("cvt.rn.bf16x2.f32 %0, %1, %2;" : "=r"(l01) : "f"(r1), "f"(r0));
    asm("cvt.rn.bf16x2.f32 %0, %1, %2;" : "=r"(l23) : "f"(r3), "f"(r2));
    *(uint2*)hp = make_uint2(h01, h23);
    *(uint2*)lp = make_uint2(l01, l23);
}

// ---------------- kernel 0: reset counters ----------------
__global__ void zero_cnt_kernel() {
    if (threadIdx.x < E_NUM) g_cnt[threadIdx.x] = 0;
}

// ---------------- kernel 1: gating + top-2 routing ----------------
__global__ void gate_kernel(const float* __restrict__ x,
                            const float* __restrict__ gw) {
    int t = blockIdx.x;
    __shared__ float xs[D_DIM];
    __shared__ float gates[E_NUM];
    int tid = threadIdx.x;
    for (int i = tid; i < D_DIM; i += blockDim.x)
        xs[i] = x[(size_t)t * D_DIM + i];
    __syncthreads();
    int wid = tid >> 5, lane = tid & 31;
    float s = 0.f;
    for (int d = lane; d < D_DIM; d += 32)
        s += xs[d] * gw[d * E_NUM + wid];
    #pragma unroll
    for (int o = 16; o > 0; o >>= 1)
        s += __shfl_down_sync(0xffffffffu, s, o);
    if (lane == 0) gates[wid] = s;
    __syncthreads();
    if (tid == 0) {
        int i0 = 0; float g0 = gates[0];
        #pragma unroll
        for (int e = 1; e < E_NUM; e++)
            if (gates[e] > g0) { g0 = gates[e]; i0 = e; }
        int i1 = -1; float g1 = -1e30f;
        #pragma unroll
        for (int e = 0; e < E_NUM; e++)
            if (e != i0 && gates[e] > g1) { g1 = gates[e]; i1 = e; }
        float ex = expf(g1 - g0);
        float w0 = 1.f / (1.f + ex);
        float w1 = ex / (1.f + ex);
        int s0 = atomicAdd(&g_cnt[i0], 1);
        int s1 = atomicAdd(&g_cnt[i1], 1);
        g_tok[i0 * CAP + s0] = t;
        g_tok[i1 * CAP + s1] = t;
        g_t2e[t * 2 + 0] = i0 * CAP + s0;
        g_t2e[t * 2 + 1] = i1 * CAP + s1;
        g_t2w[t * 2 + 0] = w0;
        g_t2w[t * 2 + 1] = w1;
    }
}

// ======================================================================
// GEMM kernels: 128x128 CTA tile, 8 warps (4 x 2), warp tile 32x64,
// mma.sync m16n8k16 bf16, 3-term split accumulation, double-buffered smem.
// ======================================================================

// ---------------- kernel 2: GEMM1 (h = x @ W1^T + b1) + SwiGLU -> split H ----------------
__global__ void __launch_bounds__(256) ffn1_mma(
    const float* __restrict__ x,
    const float* __restrict__ w1,
    const float* __restrict__ b1) {
    extern __shared__ char smem[];
    __shared__ int stok[128];
    const int e = blockIdx.z;
    const int cnt = g_cnt[e];
    const int row0 = blockIdx.y * BM;
    if (row0 >= cnt) return;
    const int c0 = blockIdx.x * BN;

    const int tid = threadIdx.x;
    const int lane = tid & 31;
    const int warp_m = (tid >> 5) & 3;
    const int warp_n = tid >> 7;
    const uint32_t sb = smem_u32(smem);

    if (tid < 128) {
        int r = row0 + tid;
        stok[tid] = (r < cnt) ? g_tok[e * CAP + r] : g_tok[e * CAP];
    }
    __syncthreads();

    // ldmatrix lane offsets
    const int lj = lane >> 3, lr = lane & 7;
    int aofs[2][2], bofs[4][2];
    #pragma unroll
    for (int mt = 0; mt < 2; mt++)
        #pragma unroll
        for (int kk = 0; kk < 2; kk++)
            aofs[mt][kk] = (warp_m * 32 + mt * 16 + (lj & 1) * 8 + lr) * RSB
                         + (kk * 16 + (lj >> 1) * 8) * 2;
    #pragma unroll
    for (int np = 0; np < 4; np++)
        #pragma unroll
        for (int kk = 0; kk < 2; kk++)
            bofs[np][kk] = (warp_n * 64 + np * 16 + (lj >> 1) * 8 + lr) * RSB
                         + (kk * 16 + (lj & 1) * 8) * 2;

    float acc[2][8][4];
    #pragma unroll
    for (int i = 0; i < 2; i++)
        #pragma unroll
        for (int j = 0; j < 8; j++)
            #pragma unroll
            for (int k = 0; k < 4; k++) acc[i][j][k] = 0.f;

    float4 regA[4], regB[4];
    const int NCHUNK = D_DIM / BK;   // 32

    // --- pipeline helpers (inlined) ---
    #define G1_LOAD(c) do { \
        int k0 = (c) * BK; \
        _Pragma("unroll") \
        for (int j = 0; j < 4; j++) { \
            int idx = tid + 256 * j; int row = idx >> 3, seg = idx & 7; \
            regA[j] = *(const float4*)(x + (size_t)stok[row] * D_DIM + k0 + seg * 4); \
            regB[j] = *(const float4*)(w1 + ((size_t)e * F2 + c0 + row) * D_DIM + k0 + seg * 4); \
        } } while (0)
    #define G1_STORE(b) do { \
        char* st = smem + (b) * STAGE; \
        _Pragma("unroll") \
        for (int j = 0; j < 4; j++) { \
            int idx = tid + 256 * j; int row = idx >> 3, seg = idx & 7; \
            int so = row * RSB + seg * 8; \
            split_store(st + so, st + ABYTES + so, regA[j]); \
            split_store(st + 2 * ABYTES + so, st + 3 * ABYTES + so, regB[j]); \
        } } while (0)

    G1_LOAD(0);
    G1_STORE(0);
    G1_LOAD(1);

    for (int c = 0; c < NCHUNK; c++) {
        __syncthreads();
        if (c + 1 < NCHUNK) G1_STORE((c + 1) & 1);
        if (c + 2 < NCHUNK) G1_LOAD(c + 2);
        uint32_t base = sb + (c & 1) * STAGE;
        #pragma unroll
        for (int kk = 0; kk < 2; kk++) {
            uint32_t ah[2][4], al[2][4];
            #pragma unroll
            for (int mt = 0; mt < 2; mt++) {
                ldsm_x4(ah[mt][0], ah[mt][1], ah[mt][2], ah[mt][3], base + aofs[mt][kk]);
                ldsm_x4(al[mt][0], al[mt][1], al[mt][2], al[mt][3], base + ABYTES + aofs[mt][kk]);
            }
            #pragma unroll
            for (int np = 0; np < 4; np++) {
                uint32_t bh[4], bl[4];
                ldsm_x4(bh[0], bh[1], bh[2], bh[3], base + 2 * ABYTES + bofs[np][kk]);
                ldsm_x4(bl[0], bl[1], bl[2], bl[3], base + 3 * ABYTES + bofs[np][kk]);
                #pragma unroll
                for (int mt = 0; mt < 2; mt++) {
                    mma_bf16(acc[mt][2 * np],     ah[mt][0], ah[mt][1], ah[mt][2], ah[mt][3], bh[0], bh[1]);
                    mma_bf16(acc[mt][2 * np + 1], ah[mt][0], ah[mt][1], ah[mt][2], ah[mt][3], bh[2], bh[3]);
                    mma_bf16(acc[mt][2 * np],     al[mt][0], al[mt][1], al[mt][2], al[mt][3], bh[0], bh[1]);
                    mma_bf16(acc[mt][2 * np + 1], al[mt][0], al[mt][1], al[mt][2], al[mt][3], bh[2], bh[3]);
                    mma_bf16(acc[mt][2 * np],     ah[mt][0], ah[mt][1], ah[mt][2], ah[mt][3], bl[0], bl[1]);
                    mma_bf16(acc[mt][2 * np + 1], ah[mt][0], ah[mt][1], ah[mt][2], ah[mt][3], bl[2], bl[3]);
                }
            }
        }
    }
    #undef G1_LOAD
    #undef G1_STORE

    // epilogue: bias + SwiGLU, write split-bf16 H
    const int rl0 = warp_m * 32 + (lane >> 2);
    const int cb0 = c0 + warp_n * 64 + (lane & 3) * 2;
    #pragma unroll
    for (int mt = 0; mt < 2; mt++) {
        #pragma unroll
        for (int dd = 0; dd < 2; dd++) {
            int lrow = rl0 + mt * 16 + dd * 8;
            if (row0 + lrow >= cnt) continue;
            size_t hb = ((size_t)e * CAP + row0 + lrow) * F_DIM;
            #pragma unroll
            for (int nt = 0; nt < 8; nt++) {
                int colp = cb0 + nt * 8;
                float g = acc[mt][nt][dd * 2]     + b1[e * F2 + colp];
                float v = acc[mt][nt][dd * 2 + 1] + b1[e * F2 + colp + 1];
                g = fminf(g, 9.0f);
                v = fmaxf(fminf(v, 9.0f), -9.0f);
                float sig = 1.0f / (1.0f + __expf(-1.702f * g));
                float h = g * sig * (v + 1.0f);
                __nv_bfloat16 hhi = __float2bfloat16(h);
                __nv_bfloat16 hlo = __float2bfloat16(h - __bfloat162float(hhi));
                g_Hh[hb + (colp >> 1)] = hhi;
                g_Hl[hb + (colp >> 1)] = hlo;
            }
        }
    }
}

// ---------------- kernel 3: GEMM2 (y = H @ W2^T + b2) ----------------
__global__ void __launch_bounds__(256) ffn2_mma(
    const float* __restrict__ w2,
    const float* __restrict__ b2) {
    extern __shared__ char smem[];
    const int e = blockIdx.z;
    const int cnt = g_cnt[e];
    const int row0 = blockIdx.y * BM;
    if (row0 >= cnt) return;
    const int d0 = blockIdx.x * BN;

    const int tid = threadIdx.x;
    const int lane = tid & 31;
    const int warp_m = (tid >> 5) & 3;
    const int warp_n = tid >> 7;
    const uint32_t sb = smem_u32(smem);

    const int lj = lane >> 3, lr = lane & 7;
    int aofs[2][2], bofs[4][2];
    #pragma unroll
    for (int mt = 0; mt < 2; mt++)
        #pragma unroll
        for (int kk = 0; kk < 2; kk++)
            aofs[mt][kk] = (warp_m * 32 + mt * 16 + (lj & 1) * 8 + lr) * RSB
                         + (kk * 16 + (lj >> 1) * 8) * 2;
    #pragma unroll
    for (int np = 0; np < 4; np++)
        #pragma unroll
        for (int kk = 0; kk < 2; kk++)
            bofs[np][kk] = (warp_n * 64 + np * 16 + (lj >> 1) * 8 + lr) * RSB
                         + (kk * 16 + (lj & 1) * 8) * 2;

    float acc[2][8][4];
    #pragma unroll
    for (int i = 0; i < 2; i++)
        #pragma unroll
        for (int j = 0; j < 8; j++)
            #pragma unroll
            for (int k = 0; k < 4; k++) acc[i][j][k] = 0.f;

    uint4 regAh[2], regAl[2];
    float4 regB[4];
    const int NCHUNK = F_DIM / BK;   // 64

    #define G2_LOAD(c) do { \
        int k0 = (c) * BK; \
        _Pragma("unroll") \
        for (int j = 0; j < 2; j++) { \
            int idx = tid + 256 * j; int row = idx >> 2, seg = idx & 3; \
            size_t ga = ((size_t)e * CAP + row0 + row) * F_DIM + k0 + seg * 8; \
            regAh[j] = *(const uint4*)(g_Hh + ga); \
            regAl[j] = *(const uint4*)(g_Hl + ga); \
        } \
        _Pragma("unroll") \
        for (int j = 0; j < 4; j++) { \
            int idx = tid + 256 * j; int row = idx >> 3, seg = idx & 7; \
            regB[j] = *(const float4*)(w2 + ((size_t)e * D_DIM + d0 + row) * F_DIM + k0 + seg * 4); \
        } } while (0)
    #define G2_STORE(b) do { \
        char* st = smem + (b) * STAGE; \
        _Pragma("unroll") \
        for (int j = 0; j < 2; j++) { \
            int idx = tid + 256 * j; int row = idx >> 2, seg = idx & 3; \
            int so = row * RSB + seg * 16; \
            *(uint4*)(st + so) = regAh[j]; \
            *(uint4*)(st + ABYTES + so) = regAl[j]; \
        } \
        _Pragma("unroll") \
        for (int j = 0; j < 4; j++) { \
            int idx = tid + 256 * j; int row = idx >> 3, seg = idx & 7; \
            int so = row * RSB + seg * 8; \
            split_store(st + 2 * ABYTES + so, st + 3 * ABYTES + so, regB[j]); \
        } } while (0)

    G2_LOAD(0);
    G2_STORE(0);
    G2_LOAD(1);

    for (int c = 0; c < NCHUNK; c++) {
        __syncthreads();
        if (c + 1 < NCHUNK) G2_STORE((c + 1) & 1);
        if (c + 2 < NCHUNK) G2_LOAD(c + 2);
        uint32_t base = sb + (c & 1) * STAGE;
        #pragma unroll
        for (int kk = 0; kk < 2; kk++) {
            uint32_t ah[2][4], al[2][4];
            #pragma unroll
            for (int mt = 0; mt < 2; mt++) {
                ldsm_x4(ah[mt][0], ah[mt][1], ah[mt][2], ah[mt][3], base + aofs[mt][kk]);
                ldsm_x4(al[mt][0], al[mt][1], al[mt][2], al[mt][3], base + ABYTES + aofs[mt][kk]);
            }
            #pragma unroll
            for (int np = 0; np < 4; np++) {
                uint32_t bh[4], bl[4];
                ldsm_x4(bh[0], bh[1], bh[2], bh[3], base + 2 * ABYTES + bofs[np][kk]);
                ldsm_x4(bl[0], bl[1], bl[2], bl[3], base + 3 * ABYTES + bofs[np][kk]);
                #pragma unroll
                for (int mt = 0; mt < 2; mt++) {
                    mma_bf16(acc[mt][2 * np],     ah[mt][0], ah[mt][1], ah[mt][2], ah[mt][3], bh[0], bh[1]);
                    mma_bf16(acc[mt][2 * np + 1], ah[mt][0], ah[mt][1], ah[mt][2], ah[mt][3], bh[2], bh[3]);
                    mma_bf16(acc[mt][2 * np],     al[mt][0], al[mt][1], al[mt][2], al[mt][3], bh[0], bh[1]);
                    mma_bf16(acc[mt][2 * np + 1], al[mt][0], al[mt][1], al[mt][2], al[mt][3], bh[2], bh[3]);
                    mma_bf16(acc[mt][2 * np],     ah[mt][0], ah[mt][1], ah[mt][2], ah[mt][3], bl[0], bl[1]);
                    mma_bf16(acc[mt][2 * np + 1], ah[mt][0], ah[mt][1], ah[mt][2], ah[mt][3], bl[2], bl[3]);
                }
            }
        }
    }
    #undef G2_LOAD
    #undef G2_STORE

    // epilogue: bias + store fp32 y
    const int rl0 = warp_m * 32 + (lane >> 2);
    const int cb0 = d0 + warp_n * 64 + (lane & 3) * 2;
    #pragma unroll
    for (int mt = 0; mt < 2; mt++) {
        #pragma unroll
        for (int dd = 0; dd < 2; dd++) {
            int lrow = rl0 + mt * 16 + dd * 8;
            if (row0 + lrow >= cnt) continue;
            float* yrow = g_y + ((size_t)e * CAP + row0 + lrow) * D_DIM;
            #pragma unroll
            for (int nt = 0; nt < 8; nt++) {
                int col = cb0 + nt * 8;
                float2 o;
                o.x = acc[mt][nt][dd * 2]     + b2[e * D_DIM + col];
                o.y = acc[mt][nt][dd * 2 + 1] + b2[e * D_DIM + col + 1];
                *(float2*)(yrow + col) = o;
            }
        }
    }
}

// ---------------- kernel 4: deterministic weighted combine ----------------
__global__ void combine_kernel(float* __restrict__ out) {
    int t = blockIdx.x;
    int   e0 = g_t2e[t * 2 + 0], e1 = g_t2e[t * 2 + 1];
    float w0 = g_t2w[t * 2 + 0], w1 = g_t2w[t * 2 + 1];
    const float* y0 = g_y + (size_t)e0 * D_DIM;
    const float* y1 = g_y + (size_t)e1 * D_DIM;
    float* o = out + (size_t)t * D_DIM;
    for (int d = threadIdx.x; d < D_DIM; d += blockDim.x)
        o[d] = w0 * y0[d] + w1 * y1[d];
}

extern "C" void kernel_launch(void* const* d_in, const int* in_sizes, int n_in,
                              void* d_out, int out_size) {
    const float* x  = (const float*)d_in[0];
    const float* gw = (const float*)d_in[1];
    const float* w1 = (const float*)d_in[2];
    const float* b1 = (const float*)d_in[3];
    const float* w2 = (const float*)d_in[4];
    const float* b2 = (const float*)d_in[5];
    float* out = (float*)d_out;

    static int configured = 0;
    if (!configured) {
        cudaFuncSetAttribute(ffn1_mma, cudaFuncAttributeMaxDynamicSharedMemorySize, SMEM_BYTES);
        cudaFuncSetAttribute(ffn2_mma, cudaFuncAttributeMaxDynamicSharedMemorySize, SMEM_BYTES);
        configured = 1;
    }

    zero_cnt_kernel<<<1, 32>>>();
    gate_kernel<<<T_TOK, 256>>>(x, gw);
    ffn1_mma<<<dim3(F2 / BN, CAP / BM, E_NUM), 256, SMEM_BYTES>>>(x, w1, b1);
    ffn2_mma<<<dim3(D_DIM / BN, CAP / BM, E_NUM), 256, SMEM_BYTES>>>(w2, b2);
    combine_kernel<<<T_TOK, 256>>>(out);
}

// round 6
// speedup vs baseline: 2.5771x; 1.1174x over previous
#include <cuda_runtime.h>
#include <cuda_bf16.h>
#include <math.h>
#include <stdint.h>

// Problem constants
#define T_TOK 4096
#define D_DIM 1024
#define E_NUM 8
#define F_DIM 2048
#define F2    4096
#define CAP   4096

// Tile config
#define BM 128
#define BN 128
#define BK 32                    // bf16 k per stage
#define RSB 80                   // smem row stride bytes (16B-aligned, ldmatrix conflict-free)
#define ABYTES (128 * RSB)       // 10240 per matrix
#define STAGE  (4 * ABYTES)      // Ah, Al, Bh, Bl = 40960
#define SMEM_BYTES (2 * STAGE)   // 81920 (2 stages)

// ---------------- scratch (device globals; no allocs allowed) ----------------
__device__ int   g_cnt[E_NUM];
__device__ int   g_tok[E_NUM * CAP];
__device__ int   g_t2e[T_TOK * 2];
__device__ float g_t2w[T_TOK * 2];
__device__ __nv_bfloat16 g_Hh[(size_t)E_NUM * CAP * F_DIM];
__device__ __nv_bfloat16 g_Hl[(size_t)E_NUM * CAP * F_DIM];
__device__ float g_y[(size_t)E_NUM * CAP * D_DIM];
// pre-split operands
__device__ __nv_bfloat16 g_xh[(size_t)T_TOK * D_DIM];
__device__ __nv_bfloat16 g_xl[(size_t)T_TOK * D_DIM];
__device__ __nv_bfloat16 g_w1h[(size_t)E_NUM * F2 * D_DIM];
__device__ __nv_bfloat16 g_w1l[(size_t)E_NUM * F2 * D_DIM];
__device__ __nv_bfloat16 g_w2h[(size_t)E_NUM * D_DIM * F_DIM];
__device__ __nv_bfloat16 g_w2l[(size_t)E_NUM * D_DIM * F_DIM];

// ---------------- helpers ----------------
__device__ __forceinline__ uint32_t smem_u32(const void* p) {
    uint32_t a;
    asm("{ .reg .u64 t; cvta.to.shared.u64 t, %1; cvt.u32.u64 %0, t; }" : "=r"(a) : "l"(p));
    return a;
}
__device__ __forceinline__ void ldsm_x4(uint32_t& r0, uint32_t& r1, uint32_t& r2, uint32_t& r3,
                                        uint32_t addr) {
    asm volatile("ldmatrix.sync.aligned.m8n8.x4.shared.b16 {%0,%1,%2,%3}, [%4];"
                 : "=r"(r0), "=r"(r1), "=r"(r2), "=r"(r3) : "r"(addr));
}
__device__ __forceinline__ void mma_bf16(float* c,
                                         uint32_t a0, uint32_t a1, uint32_t a2, uint32_t a3,
                                         uint32_t b0, uint32_t b1) {
    asm volatile("mma.sync.aligned.m16n8k16.row.col.f32.bf16.bf16.f32 "
                 "{%0,%1,%2,%3}, {%4,%5,%6,%7}, {%8,%9}, {%0,%1,%2,%3};"
                 : "+f"(c[0]), "+f"(c[1]), "+f"(c[2]), "+f"(c[3])
                 : "r"(a0), "r"(a1), "r"(a2), "r"(a3), "r"(b0), "r"(b1));
}
#define CP16(dst, src) \
    asm volatile("cp.async.cg.shared.global [%0], [%1], 16;" :: "r"(dst), "l"(src) : "memory")
#define CP_COMMIT() asm volatile("cp.async.commit_group;" ::: "memory")
#define CP_WAIT1()  asm volatile("cp.async.wait_group 1;" ::: "memory")

// fp32x4 -> split bf16 hi/lo (4 bf16 = 8B each)
__device__ __forceinline__ void split_store(char* hp, char* lp, float4 v) {
    uint32_t h01, h23, l01, l23;
    asm("cvt.rn.bf16x2.f32 %0, %1, %2;" : "=r"(h01) : "f"(v.y), "f"(v.x));
    asm("cvt.rn.bf16x2.f32 %0, %1, %2;" : "=r"(h23) : "f"(v.w), "f"(v.z));
    float r0 = v.x - __uint_as_float(h01 << 16);
    float r1 = v.y - __uint_as_float(h01 & 0xFFFF0000u);
    float r2 = v.z - __uint_as_float(h23 << 16);
    float r3 = v.w - __uint_as_float(h23 & 0xFFFF0000u);
    asm("cvt.rn.bf16x2.f32 %0, %1, %2;" : "=r"(l01) : "f"(r1), "f"(r0));
    asm("cvt.rn.bf16x2.f32 %0, %1, %2;" : "=r"(l23) : "f"(r3), "f"(r2));
    *(uint2*)hp = make_uint2(h01, h23);
    *(uint2*)lp = make_uint2(l01, l23);
}

// ---------------- kernel: fp32 -> split bf16 (grid-stride over float4) ----------------
__global__ void split_kernel(const float* __restrict__ src,
                             __nv_bfloat16* __restrict__ h,
                             __nv_bfloat16* __restrict__ l, int n4) {
    int i = blockIdx.x * blockDim.x + threadIdx.x;
    int stride = gridDim.x * blockDim.x;
    for (; i < n4; i += stride) {
        float4 v = ((const float4*)src)[i];
        split_store((char*)(h + 4 * (size_t)i), (char*)(l + 4 * (size_t)i), v);
    }
}

// ---------------- kernel 0: reset counters ----------------
__global__ void zero_cnt_kernel() {
    if (threadIdx.x < E_NUM) g_cnt[threadIdx.x] = 0;
}

// ---------------- kernel 1: gating + top-2 routing ----------------
__global__ void gate_kernel(const float* __restrict__ x,
                            const float* __restrict__ gw) {
    int t = blockIdx.x;
    __shared__ float xs[D_DIM];
    __shared__ float gates[E_NUM];
    int tid = threadIdx.x;
    for (int i = tid; i < D_DIM; i += blockDim.x)
        xs[i] = x[(size_t)t * D_DIM + i];
    __syncthreads();
    int wid = tid >> 5, lane = tid & 31;
    float s = 0.f;
    for (int d = lane; d < D_DIM; d += 32)
        s += xs[d] * gw[d * E_NUM + wid];
    #pragma unroll
    for (int o = 16; o > 0; o >>= 1)
        s += __shfl_down_sync(0xffffffffu, s, o);
    if (lane == 0) gates[wid] = s;
    __syncthreads();
    if (tid == 0) {
        int i0 = 0; float g0 = gates[0];
        #pragma unroll
        for (int e = 1; e < E_NUM; e++)
            if (gates[e] > g0) { g0 = gates[e]; i0 = e; }
        int i1 = -1; float g1 = -1e30f;
        #pragma unroll
        for (int e = 0; e < E_NUM; e++)
            if (e != i0 && gates[e] > g1) { g1 = gates[e]; i1 = e; }
        float ex = expf(g1 - g0);
        float w0 = 1.f / (1.f + ex);
        float w1 = ex / (1.f + ex);
        int s0 = atomicAdd(&g_cnt[i0], 1);
        int s1 = atomicAdd(&g_cnt[i1], 1);
        g_tok[i0 * CAP + s0] = t;
        g_tok[i1 * CAP + s1] = t;
        g_t2e[t * 2 + 0] = i0 * CAP + s0;
        g_t2e[t * 2 + 1] = i1 * CAP + s1;
        g_t2w[t * 2 + 0] = w0;
        g_t2w[t * 2 + 1] = w1;
    }
}

// ======================================================================
// GEMMs: 128x128 CTA tile, 8 warps (4x2), warp tile 32x64, m16n8k16 bf16,
// 3-term split accumulation, cp.async 2-stage pipeline, 2 CTAs/SM.
// ======================================================================

#define MMA_COMPUTE(base) do { \
    _Pragma("unroll") \
    for (int kk = 0; kk < 2; kk++) { \
        uint32_t ah[2][4], al[2][4]; \
        _Pragma("unroll") \
        for (int mt = 0; mt < 2; mt++) { \
            ldsm_x4(ah[mt][0], ah[mt][1], ah[mt][2], ah[mt][3], (base) + aofs[mt][kk]); \
            ldsm_x4(al[mt][0], al[mt][1], al[mt][2], al[mt][3], (base) + ABYTES + aofs[mt][kk]); \
        } \
        _Pragma("unroll") \
        for (int np = 0; np < 4; np++) { \
            uint32_t bh[4], bl[4]; \
            ldsm_x4(bh[0], bh[1], bh[2], bh[3], (base) + 2 * ABYTES + bofs[np][kk]); \
            ldsm_x4(bl[0], bl[1], bl[2], bl[3], (base) + 3 * ABYTES + bofs[np][kk]); \
            _Pragma("unroll") \
            for (int mt = 0; mt < 2; mt++) { \
                mma_bf16(acc[mt][2 * np],     ah[mt][0], ah[mt][1], ah[mt][2], ah[mt][3], bh[0], bh[1]); \
                mma_bf16(acc[mt][2 * np + 1], ah[mt][0], ah[mt][1], ah[mt][2], ah[mt][3], bh[2], bh[3]); \
                mma_bf16(acc[mt][2 * np],     al[mt][0], al[mt][1], al[mt][2], al[mt][3], bh[0], bh[1]); \
                mma_bf16(acc[mt][2 * np + 1], al[mt][0], al[mt][1], al[mt][2], al[mt][3], bh[2], bh[3]); \
                mma_bf16(acc[mt][2 * np],     ah[mt][0], ah[mt][1], ah[mt][2], ah[mt][3], bl[0], bl[1]); \
                mma_bf16(acc[mt][2 * np + 1], ah[mt][0], ah[mt][1], ah[mt][2], ah[mt][3], bl[2], bl[3]); \
            } \
        } \
    } } while (0)

#define LDSM_OFFSETS() \
    const int lj = lane >> 3, lr = lane & 7; \
    int aofs[2][2], bofs[4][2]; \
    _Pragma("unroll") \
    for (int mt = 0; mt < 2; mt++) \
        _Pragma("unroll") \
        for (int kk = 0; kk < 2; kk++) \
            aofs[mt][kk] = (warp_m * 32 + mt * 16 + (lj & 1) * 8 + lr) * RSB \
                         + (kk * 16 + (lj >> 1) * 8) * 2; \
    _Pragma("unroll") \
    for (int np = 0; np < 4; np++) \
        _Pragma("unroll") \
        for (int kk = 0; kk < 2; kk++) \
            bofs[np][kk] = (warp_n * 64 + np * 16 + (lj >> 1) * 8 + lr) * RSB \
                         + (kk * 16 + (lj & 1) * 8) * 2

// ---------------- kernel 2: GEMM1 (h = x @ W1^T + b1) + SwiGLU -> split H ----------------
__global__ void __launch_bounds__(256, 2) ffn1_mma(
    const float* __restrict__ b1) {
    extern __shared__ char smem[];
    __shared__ int stok[128];
    const int e = blockIdx.z;
    const int cnt = g_cnt[e];
    const int row0 = blockIdx.y * BM;
    if (row0 >= cnt) return;
    const int c0 = blockIdx.x * BN;

    const int tid = threadIdx.x;
    const int lane = tid & 31;
    const int warp_m = (tid >> 5) & 3;
    const int warp_n = tid >> 7;
    const uint32_t sb = smem_u32(smem);

    if (tid < 128) {
        int r = row0 + tid;
        stok[tid] = (r < cnt) ? g_tok[e * CAP + r] : g_tok[e * CAP];
    }
    __syncthreads();

    LDSM_OFFSETS();

    float acc[2][8][4];
    #pragma unroll
    for (int i = 0; i < 2; i++)
        #pragma unroll
        for (int j = 0; j < 8; j++)
            #pragma unroll
            for (int k = 0; k < 4; k++) acc[i][j][k] = 0.f;

    const int NCHUNK = D_DIM / BK;   // 32

    #define G1_ISSUE(c, buf) do { \
        int k0 = (c) * BK; \
        uint32_t st = sb + (buf) * STAGE; \
        _Pragma("unroll") \
        for (int j = 0; j < 2; j++) { \
            int idx = tid + 256 * j; int row = idx >> 2, seg = idx & 3; \
            uint32_t so = st + row * RSB + seg * 16; \
            size_t ao = (size_t)stok[row] * D_DIM + k0 + seg * 8; \
            size_t bo = ((size_t)e * F2 + c0 + row) * D_DIM + k0 + seg * 8; \
            CP16(so,              g_xh  + ao); \
            CP16(so + ABYTES,     g_xl  + ao); \
            CP16(so + 2 * ABYTES, g_w1h + bo); \
            CP16(so + 3 * ABYTES, g_w1l + bo); \
        } } while (0)

    G1_ISSUE(0, 0); CP_COMMIT();
    G1_ISSUE(1, 1); CP_COMMIT();

    #pragma unroll 1
    for (int c = 0; c < NCHUNK; c++) {
        CP_WAIT1();
        __syncthreads();
        uint32_t base = sb + (c & 1) * STAGE;
        MMA_COMPUTE(base);
        __syncthreads();
        if (c + 2 < NCHUNK) G1_ISSUE(c + 2, c & 1);
        CP_COMMIT();
    }
    #undef G1_ISSUE

    // epilogue: bias + SwiGLU, write split-bf16 H
    const int rl0 = warp_m * 32 + (lane >> 2);
    const int cb0 = c0 + warp_n * 64 + (lane & 3) * 2;
    #pragma unroll
    for (int mt = 0; mt < 2; mt++) {
        #pragma unroll
        for (int dd = 0; dd < 2; dd++) {
            int lrow = rl0 + mt * 16 + dd * 8;
            if (row0 + lrow >= cnt) continue;
            size_t hb = ((size_t)e * CAP + row0 + lrow) * F_DIM;
            #pragma unroll
            for (int nt = 0; nt < 8; nt++) {
                int colp = cb0 + nt * 8;
                float g = acc[mt][nt][dd * 2]     + b1[e * F2 + colp];
                float v = acc[mt][nt][dd * 2 + 1] + b1[e * F2 + colp + 1];
                g = fminf(g, 9.0f);
                v = fmaxf(fminf(v, 9.0f), -9.0f);
                float sig = 1.0f / (1.0f + __expf(-1.702f * g));
                float h = g * sig * (v + 1.0f);
                __nv_bfloat16 hhi = __float2bfloat16(h);
                __nv_bfloat16 hlo = __float2bfloat16(h - __bfloat162float(hhi));
                g_Hh[hb + (colp >> 1)] = hhi;
                g_Hl[hb + (colp >> 1)] = hlo;
            }
        }
    }
}

// ---------------- kernel 3: GEMM2 (y = H @ W2^T + b2) ----------------
__global__ void __launch_bounds__(256, 2) ffn2_mma(
    const float* __restrict__ b2) {
    extern __shared__ char smem[];
    const int e = blockIdx.z;
    const int cnt = g_cnt[e];
    const int row0 = blockIdx.y * BM;
    if (row0 >= cnt) return;
    const int d0 = blockIdx.x * BN;

    const int tid = threadIdx.x;
    const int lane = tid & 31;
    const int warp_m = (tid >> 5) & 3;
    const int warp_n = tid >> 7;
    const uint32_t sb = smem_u32(smem);

    LDSM_OFFSETS();

    float acc[2][8][4];
    #pragma unroll
    for (int i = 0; i < 2; i++)
        #pragma unroll
        for (int j = 0; j < 8; j++)
            #pragma unroll
            for (int k = 0; k < 4; k++) acc[i][j][k] = 0.f;

    const int NCHUNK = F_DIM / BK;   // 64

    #define G2_ISSUE(c, buf) do { \
        int k0 = (c) * BK; \
        uint32_t st = sb + (buf) * STAGE; \
        _Pragma("unroll") \
        for (int j = 0; j < 2; j++) { \
            int idx = tid + 256 * j; int row = idx >> 2, seg = idx & 3; \
            uint32_t so = st + row * RSB + seg * 16; \
            size_t ao = ((size_t)e * CAP + row0 + row) * F_DIM + k0 + seg * 8; \
            size_t bo = ((size_t)e * D_DIM + d0 + row) * F_DIM + k0 + seg * 8; \
            CP16(so,              g_Hh  + ao); \
            CP16(so + ABYTES,     g_Hl  + ao); \
            CP16(so + 2 * ABYTES, g_w2h + bo); \
            CP16(so + 3 * ABYTES, g_w2l + bo); \
        } } while (0)

    G2_ISSUE(0, 0); CP_COMMIT();
    G2_ISSUE(1, 1); CP_COMMIT();

    #pragma unroll 1
    for (int c = 0; c < NCHUNK; c++) {
        CP_WAIT1();
        __syncthreads();
        uint32_t base = sb + (c & 1) * STAGE;
        MMA_COMPUTE(base);
        __syncthreads();
        if (c + 2 < NCHUNK) G2_ISSUE(c + 2, c & 1);
        CP_COMMIT();
    }
    #undef G2_ISSUE

    // epilogue: bias + store fp32 y
    const int rl0 = warp_m * 32 + (lane >> 2);
    const int cb0 = d0 + warp_n * 64 + (lane & 3) * 2;
    #pragma unroll
    for (int mt = 0; mt < 2; mt++) {
        #pragma unroll
        for (int dd = 0; dd < 2; dd++) {
            int lrow = rl0 + mt * 16 + dd * 8;
            if (row0 + lrow >= cnt) continue;
            float* yrow = g_y + ((size_t)e * CAP + row0 + lrow) * D_DIM;
            #pragma unroll
            for (int nt = 0; nt < 8; nt++) {
                int col = cb0 + nt * 8;
                float2 o;
                o.x = acc[mt][nt][dd * 2]     + b2[e * D_DIM + col];
                o.y = acc[mt][nt][dd * 2 + 1] + b2[e * D_DIM + col + 1];
                *(float2*)(yrow + col) = o;
            }
        }
    }
}

// ---------------- kernel 4: deterministic weighted combine ----------------
__global__ void combine_kernel(float* __restrict__ out) {
    int t = blockIdx.x;
    int   e0 = g_t2e[t * 2 + 0], e1 = g_t2e[t * 2 + 1];
    float w0 = g_t2w[t * 2 + 0], w1 = g_t2w[t * 2 + 1];
    const float* y0 = g_y + (size_t)e0 * D_DIM;
    const float* y1 = g_y + (size_t)e1 * D_DIM;
    float* o = out + (size_t)t * D_DIM;
    for (int d = threadIdx.x; d < D_DIM; d += blockDim.x)
        o[d] = w0 * y0[d] + w1 * y1[d];
}

extern "C" void kernel_launch(void* const* d_in, const int* in_sizes, int n_in,
                              void* d_out, int out_size) {
    const float* x  = (const float*)d_in[0];
    const float* gw = (const float*)d_in[1];
    const float* w1 = (const float*)d_in[2];
    const float* b1 = (const float*)d_in[3];
    const float* w2 = (const float*)d_in[4];
    const float* b2 = (const float*)d_in[5];
    float* out = (float*)d_out;

    static int configured = 0;
    if (!configured) {
        cudaFuncSetAttribute(ffn1_mma, cudaFuncAttributeMaxDynamicSharedMemorySize, SMEM_BYTES);
        cudaFuncSetAttribute(ffn2_mma, cudaFuncAttributeMaxDynamicSharedMemorySize, SMEM_BYTES);
        configured = 1;
    }

    __nv_bfloat16 *xh, *xl, *w1h, *w1l, *w2h, *w2l;
    cudaGetSymbolAddress((void**)&xh,  g_xh);
    cudaGetSymbolAddress((void**)&xl,  g_xl);
    cudaGetSymbolAddress((void**)&w1h, g_w1h);
    cudaGetSymbolAddress((void**)&w1l, g_w1l);
    cudaGetSymbolAddress((void**)&w2h, g_w2h);
    cudaGetSymbolAddress((void**)&w2l, g_w2l);

    zero_cnt_kernel<<<1, 32>>>();
    gate_kernel<<<T_TOK, 256>>>(x, gw);
    split_kernel<<<4096, 256>>>(x,  xh,  xl,  (T_TOK * D_DIM) / 4);
    split_kernel<<<8192, 256>>>(w1, w1h, w1l, (E_NUM * F2 * D_DIM) / 4);
    split_kernel<<<8192, 256>>>(w2, w2h, w2l, (E_NUM * D_DIM * F_DIM) / 4);
    ffn1_mma<<<dim3(F2 / BN, CAP / BM, E_NUM), 256, SMEM_BYTES>>>(b1);
    ffn2_mma<<<dim3(D_DIM / BN, CAP / BM, E_NUM), 256, SMEM_BYTES>>>(b2);
    combine_kernel<<<T_TOK, 256>>>(out);
}

// round 7
// speedup vs baseline: 2.8659x; 1.1121x over previous
#include <cuda_runtime.h>
#include <cuda_bf16.h>
#include <math.h>
#include <stdint.h>

// Problem constants
#define T_TOK 4096
#define D_DIM 1024
#define E_NUM 8
#define F_DIM 2048
#define F2    4096
#define CAP   4096

// Tile config: 128x128 CTA tile, BK=32, packed hi|lo rows (128B), 3 stages
#define BM 128
#define BN 128
#define BK 32
#define MAT   16384              // one matrix pair (128 rows x 128B)
#define STAGE 32768              // A-pair + B-pair
#define NSTAGE 3
#define SMEM_BYTES (NSTAGE * STAGE)   // 98304

// ---------------- scratch (device globals; no allocs allowed) ----------------
__device__ int   g_cnt[E_NUM];
__device__ int   g_tok[E_NUM * CAP];
__device__ int   g_t2e[T_TOK * 2];
__device__ float g_t2w[T_TOK * 2];
__device__ __nv_bfloat16 g_Hh[(size_t)E_NUM * CAP * F_DIM];
__device__ __nv_bfloat16 g_Hl[(size_t)E_NUM * CAP * F_DIM];
__device__ float g_y[(size_t)E_NUM * CAP * D_DIM];
// pre-split operands
__device__ __nv_bfloat16 g_xh[(size_t)T_TOK * D_DIM];
__device__ __nv_bfloat16 g_xl[(size_t)T_TOK * D_DIM];
__device__ __nv_bfloat16 g_w1h[(size_t)E_NUM * F2 * D_DIM];
__device__ __nv_bfloat16 g_w1l[(size_t)E_NUM * F2 * D_DIM];
__device__ __nv_bfloat16 g_w2h[(size_t)E_NUM * D_DIM * F_DIM];
__device__ __nv_bfloat16 g_w2l[(size_t)E_NUM * D_DIM * F_DIM];

// ---------------- helpers ----------------
__device__ __forceinline__ uint32_t smem_u32(const void* p) {
    uint32_t a;
    asm("{ .reg .u64 t; cvta.to.shared.u64 t, %1; cvt.u32.u64 %0, t; }" : "=r"(a) : "l"(p));
    return a;
}
__device__ __forceinline__ void ldsm_x4(uint32_t& r0, uint32_t& r1, uint32_t& r2, uint32_t& r3,
                                        uint32_t addr) {
    asm volatile("ldmatrix.sync.aligned.m8n8.x4.shared.b16 {%0,%1,%2,%3}, [%4];"
                 : "=r"(r0), "=r"(r1), "=r"(r2), "=r"(r3) : "r"(addr));
}
__device__ __forceinline__ void mma_bf16(float* c,
                                         uint32_t a0, uint32_t a1, uint32_t a2, uint32_t a3,
                                         uint32_t b0, uint32_t b1) {
    asm volatile("mma.sync.aligned.m16n8k16.row.col.f32.bf16.bf16.f32 "
                 "{%0,%1,%2,%3}, {%4,%5,%6,%7}, {%8,%9}, {%0,%1,%2,%3};"
                 : "+f"(c[0]), "+f"(c[1]), "+f"(c[2]), "+f"(c[3])
                 : "r"(a0), "r"(a1), "r"(a2), "r"(a3), "r"(b0), "r"(b1));
}
#define CP16(dst, src) \
    asm volatile("cp.async.cg.shared.global [%0], [%1], 16;" :: "r"(dst), "l"(src) : "memory")
#define CP_COMMIT() asm volatile("cp.async.commit_group;" ::: "memory")
#define CP_WAIT2()  asm volatile("cp.async.wait_group 2;" ::: "memory")

// fp32x4 -> split bf16 hi/lo (4 bf16 = 8B each)
__device__ __forceinline__ void split_store(char* hp, char* lp, float4 v) {
    uint32_t h01, h23, l01, l23;
    asm("cvt.rn.bf16x2.f32 %0, %1, %2;" : "=r"(h01) : "f"(v.y), "f"(v.x));
    asm("cvt.rn.bf16x2.f32 %0, %1, %2;" : "=r"(h23) : "f"(v.w), "f"(v.z));
    float r0 = v.x - __uint_as_float(h01 << 16);
    float r1 = v.y - __uint_as_float(h01 & 0xFFFF0000u);
    float r2 = v.z - __uint_as_float(h23 << 16);
    float r3 = v.w - __uint_as_float(h23 & 0xFFFF0000u);
    asm("cvt.rn.bf16x2.f32 %0, %1, %2;" : "=r"(l01) : "f"(r1), "f"(r0));
    asm("cvt.rn.bf16x2.f32 %0, %1, %2;" : "=r"(l23) : "f"(r3), "f"(r2));
    *(uint2*)hp = make_uint2(h01, h23);
    *(uint2*)lp = make_uint2(l01, l23);
}

// ---------------- kernel: fp32 -> split bf16 (grid-stride over float4) ----------------
__global__ void split_kernel(const float* __restrict__ src,
                             __nv_bfloat16* __restrict__ h,
                             __nv_bfloat16* __restrict__ l, int n4) {
    int i = blockIdx.x * blockDim.x + threadIdx.x;
    int stride = gridDim.x * blockDim.x;
    for (; i < n4; i += stride) {
        float4 v = ((const float4*)src)[i];
        split_store((char*)(h + 4 * (size_t)i), (char*)(l + 4 * (size_t)i), v);
    }
}

// ---------------- kernel 0: reset counters ----------------
__global__ void zero_cnt_kernel() {
    if (threadIdx.x < E_NUM) g_cnt[threadIdx.x] = 0;
}

// ---------------- kernel 1: gating + top-2 routing ----------------
__global__ void gate_kernel(const float* __restrict__ x,
                            const float* __restrict__ gw) {
    int t = blockIdx.x;
    __shared__ float xs[D_DIM];
    __shared__ float gates[E_NUM];
    int tid = threadIdx.x;
    for (int i = tid; i < D_DIM; i += blockDim.x)
        xs[i] = x[(size_t)t * D_DIM + i];
    __syncthreads();
    int wid = tid >> 5, lane = tid & 31;
    float s = 0.f;
    for (int d = lane; d < D_DIM; d += 32)
        s += xs[d] * gw[d * E_NUM + wid];
    #pragma unroll
    for (int o = 16; o > 0; o >>= 1)
        s += __shfl_down_sync(0xffffffffu, s, o);
    if (lane == 0) gates[wid] = s;
    __syncthreads();
    if (tid == 0) {
        int i0 = 0; float g0 = gates[0];
        #pragma unroll
        for (int e = 1; e < E_NUM; e++)
            if (gates[e] > g0) { g0 = gates[e]; i0 = e; }
        int i1 = -1; float g1 = -1e30f;
        #pragma unroll
        for (int e = 0; e < E_NUM; e++)
            if (e != i0 && gates[e] > g1) { g1 = gates[e]; i1 = e; }
        float ex = expf(g1 - g0);
        float w0 = 1.f / (1.f + ex);
        float w1 = ex / (1.f + ex);
        int s0 = atomicAdd(&g_cnt[i0], 1);
        int s1 = atomicAdd(&g_cnt[i1], 1);
        g_tok[i0 * CAP + s0] = t;
        g_tok[i1 * CAP + s1] = t;
        g_t2e[t * 2 + 0] = i0 * CAP + s0;
        g_t2e[t * 2 + 1] = i1 * CAP + s1;
        g_t2w[t * 2 + 0] = w0;
        g_t2w[t * 2 + 1] = w1;
    }
}

// ======================================================================
// GEMMs: 128x128 CTA tile, 8 warps (4x2), warp tile 32x64, m16n8k16 bf16,
// 3-term split accumulation. Packed hi|lo 128B rows, SW128 XOR swizzle,
// 3-stage cp.async pipeline, 2 CTAs/SM. lo fragment address = hi ^ 64.
// ======================================================================

// swizzled byte offset within a matrix: row in [0,128), chunk16 in [0,8)
#define SWOFF(row, ch) ((row) * 128 + (((ch) * 16) ^ (((row) & 7) << 4)))

#define LDSM_OFFSETS() \
    const int lj = lane >> 3, lr = lane & 7; \
    int aofs[2][2], bofs[4][2]; \
    _Pragma("unroll") \
    for (int mt = 0; mt < 2; mt++) \
        _Pragma("unroll") \
        for (int kk = 0; kk < 2; kk++) { \
            int ra = warp_m * 32 + mt * 16 + (lj & 1) * 8 + lr; \
            aofs[mt][kk] = SWOFF(ra, kk * 2 + (lj >> 1)); \
        } \
    _Pragma("unroll") \
    for (int np = 0; np < 4; np++) \
        _Pragma("unroll") \
        for (int kk = 0; kk < 2; kk++) { \
            int rb = warp_n * 64 + np * 16 + (lj >> 1) * 8 + lr; \
            bofs[np][kk] = MAT + SWOFF(rb, kk * 2 + (lj & 1)); \
        }

#define MMA_COMPUTE(base) do { \
    _Pragma("unroll") \
    for (int kk = 0; kk < 2; kk++) { \
        uint32_t ah[2][4], al[2][4]; \
        _Pragma("unroll") \
        for (int mt = 0; mt < 2; mt++) { \
            uint32_t addr = (base) + aofs[mt][kk]; \
            ldsm_x4(ah[mt][0], ah[mt][1], ah[mt][2], ah[mt][3], addr); \
            ldsm_x4(al[mt][0], al[mt][1], al[mt][2], al[mt][3], addr ^ 64); \
        } \
        _Pragma("unroll") \
        for (int np = 0; np < 4; np++) { \
            uint32_t bh[4], bl[4]; \
            uint32_t addr = (base) + bofs[np][kk]; \
            ldsm_x4(bh[0], bh[1], bh[2], bh[3], addr); \
            ldsm_x4(bl[0], bl[1], bl[2], bl[3], addr ^ 64); \
            _Pragma("unroll") \
            for (int mt = 0; mt < 2; mt++) { \
                mma_bf16(acc[mt][2 * np],     ah[mt][0], ah[mt][1], ah[mt][2], ah[mt][3], bh[0], bh[1]); \
                mma_bf16(acc[mt][2 * np + 1], ah[mt][0], ah[mt][1], ah[mt][2], ah[mt][3], bh[2], bh[3]); \
                mma_bf16(acc[mt][2 * np],     al[mt][0], al[mt][1], al[mt][2], al[mt][3], bh[0], bh[1]); \
                mma_bf16(acc[mt][2 * np + 1], al[mt][0], al[mt][1], al[mt][2], al[mt][3], bh[2], bh[3]); \
                mma_bf16(acc[mt][2 * np],     ah[mt][0], ah[mt][1], ah[mt][2], ah[mt][3], bl[0], bl[1]); \
                mma_bf16(acc[mt][2 * np + 1], ah[mt][0], ah[mt][1], ah[mt][2], ah[mt][3], bl[2], bl[3]); \
            } \
        } \
    } } while (0)

// ---------------- kernel 2: GEMM1 (h = x @ W1^T + b1) + SwiGLU -> split H ----------------
__global__ void __launch_bounds__(256, 2) ffn1_mma(
    const float* __restrict__ b1) {
    extern __shared__ char smem[];
    __shared__ int stok[128];
    const int e = blockIdx.z;
    const int cnt = g_cnt[e];
    const int row0 = blockIdx.y * BM;
    if (row0 >= cnt) return;
    const int c0 = blockIdx.x * BN;

    const int tid = threadIdx.x;
    const int lane = tid & 31;
    const int warp_m = (tid >> 5) & 3;
    const int warp_n = tid >> 7;
    const uint32_t sb = smem_u32(smem);

    if (tid < 128) {
        int r = row0 + tid;
        stok[tid] = (r < cnt) ? g_tok[e * CAP + r] : g_tok[e * CAP];
    }
    __syncthreads();

    LDSM_OFFSETS();

    float acc[2][8][4];
    #pragma unroll
    for (int i = 0; i < 2; i++)
        #pragma unroll
        for (int j = 0; j < 8; j++)
            #pragma unroll
            for (int k = 0; k < 4; k++) acc[i][j][k] = 0.f;

    const int NCHUNK = D_DIM / BK;   // 32

    // per-thread static copy mapping: 1024 chunks per matrix pair, 4 per thread
    #define G1_ISSUE(c, buf) do { \
        int k0 = (c) * BK; \
        uint32_t st = sb + (buf) * STAGE; \
        _Pragma("unroll") \
        for (int j = 0; j < 4; j++) { \
            int idx = tid + 256 * j; \
            int row = idx >> 3, ch = idx & 7; \
            int seg = ch & 3; \
            uint32_t dof = SWOFF(row, ch); \
            size_t ka = (size_t)stok[row] * D_DIM + k0 + seg * 8; \
            size_t kb = ((size_t)e * F2 + c0 + row) * D_DIM + k0 + seg * 8; \
            const __nv_bfloat16* pa = (ch < 4) ? (g_xh  + ka) : (g_xl  + ka); \
            const __nv_bfloat16* pb = (ch < 4) ? (g_w1h + kb) : (g_w1l + kb); \
            CP16(st + dof,       pa); \
            CP16(st + MAT + dof, pb); \
        } } while (0)

    G1_ISSUE(0, 0); CP_COMMIT();
    G1_ISSUE(1, 1); CP_COMMIT();
    G1_ISSUE(2, 2); CP_COMMIT();

    int buf = 0;
    #pragma unroll 1
    for (int c = 0; c < NCHUNK; c++) {
        CP_WAIT2();
        __syncthreads();
        MMA_COMPUTE(sb + buf * STAGE);
        __syncthreads();
        if (c + 3 < NCHUNK) G1_ISSUE(c + 3, buf);
        CP_COMMIT();
        buf = (buf == 2) ? 0 : buf + 1;
    }
    #undef G1_ISSUE

    // epilogue: bias + SwiGLU, write split-bf16 H
    const int rl0 = warp_m * 32 + (lane >> 2);
    const int cb0 = c0 + warp_n * 64 + (lane & 3) * 2;
    #pragma unroll
    for (int mt = 0; mt < 2; mt++) {
        #pragma unroll
        for (int dd = 0; dd < 2; dd++) {
            int lrow = rl0 + mt * 16 + dd * 8;
            if (row0 + lrow >= cnt) continue;
            size_t hb = ((size_t)e * CAP + row0 + lrow) * F_DIM;
            #pragma unroll
            for (int nt = 0; nt < 8; nt++) {
                int colp = cb0 + nt * 8;
                float g = acc[mt][nt][dd * 2]     + b1[e * F2 + colp];
                float v = acc[mt][nt][dd * 2 + 1] + b1[e * F2 + colp + 1];
                g = fminf(g, 9.0f);
                v = fmaxf(fminf(v, 9.0f), -9.0f);
                float sig = 1.0f / (1.0f + __expf(-1.702f * g));
                float h = g * sig * (v + 1.0f);
                __nv_bfloat16 hhi = __float2bfloat16(h);
                __nv_bfloat16 hlo = __float2bfloat16(h - __bfloat162float(hhi));
                g_Hh[hb + (colp >> 1)] = hhi;
                g_Hl[hb + (colp >> 1)] = hlo;
            }
        }
    }
}

// ---------------- kernel 3: GEMM2 (y = H @ W2^T + b2) ----------------
__global__ void __launch_bounds__(256, 2) ffn2_mma(
    const float* __restrict__ b2) {
    extern __shared__ char smem[];
    const int e = blockIdx.z;
    const int cnt = g_cnt[e];
    const int row0 = blockIdx.y * BM;
    if (row0 >= cnt) return;
    const int d0 = blockIdx.x * BN;

    const int tid = threadIdx.x;
    const int lane = tid & 31;
    const int warp_m = (tid >> 5) & 3;
    const int warp_n = tid >> 7;
    const uint32_t sb = smem_u32(smem);

    LDSM_OFFSETS();

    float acc[2][8][4];
    #pragma unroll
    for (int i = 0; i < 2; i++)
        #pragma unroll
        for (int j = 0; j < 8; j++)
            #pragma unroll
            for (int k = 0; k < 4; k++) acc[i][j][k] = 0.f;

    const int NCHUNK = F_DIM / BK;   // 64

    #define G2_ISSUE(c, buf) do { \
        int k0 = (c) * BK; \
        uint32_t st = sb + (buf) * STAGE; \
        _Pragma("unroll") \
        for (int j = 0; j < 4; j++) { \
            int idx = tid + 256 * j; \
            int row = idx >> 3, ch = idx & 7; \
            int seg = ch & 3; \
            uint32_t dof = SWOFF(row, ch); \
            size_t ka = ((size_t)e * CAP + row0 + row) * F_DIM + k0 + seg * 8; \
            size_t kb = ((size_t)e * D_DIM + d0 + row) * F_DIM + k0 + seg * 8; \
            const __nv_bfloat16* pa = (ch < 4) ? (g_Hh  + ka) : (g_Hl  + ka); \
            const __nv_bfloat16* pb = (ch < 4) ? (g_w2h + kb) : (g_w2l + kb); \
            CP16(st + dof,       pa); \
            CP16(st + MAT + dof, pb); \
        } } while (0)

    G2_ISSUE(0, 0); CP_COMMIT();
    G2_ISSUE(1, 1); CP_COMMIT();
    G2_ISSUE(2, 2); CP_COMMIT();

    int buf = 0;
    #pragma unroll 1
    for (int c = 0; c < NCHUNK; c++) {
        CP_WAIT2();
        __syncthreads();
        MMA_COMPUTE(sb + buf * STAGE);
        __syncthreads();
        if (c + 3 < NCHUNK) G2_ISSUE(c + 3, buf);
        CP_COMMIT();
        buf = (buf == 2) ? 0 : buf + 1;
    }
    #undef G2_ISSUE

    // epilogue: bias + store fp32 y
    const int rl0 = warp_m * 32 + (lane >> 2);
    const int cb0 = d0 + warp_n * 64 + (lane & 3) * 2;
    #pragma unroll
    for (int mt = 0; mt < 2; mt++) {
        #pragma unroll
        for (int dd = 0; dd < 2; dd++) {
            int lrow = rl0 + mt * 16 + dd * 8;
            if (row0 + lrow >= cnt) continue;
            float* yrow = g_y + ((size_t)e * CAP + row0 + lrow) * D_DIM;
            #pragma unroll
            for (int nt = 0; nt < 8; nt++) {
                int col = cb0 + nt * 8;
                float2 o;
                o.x = acc[mt][nt][dd * 2]     + b2[e * D_DIM + col];
                o.y = acc[mt][nt][dd * 2 + 1] + b2[e * D_DIM + col + 1];
                *(float2*)(yrow + col) = o;
            }
        }
    }
}

// ---------------- kernel 4: deterministic weighted combine ----------------
__global__ void combine_kernel(float* __restrict__ out) {
    int t = blockIdx.x;
    int   e0 = g_t2e[t * 2 + 0], e1 = g_t2e[t * 2 + 1];
    float w0 = g_t2w[t * 2 + 0], w1 = g_t2w[t * 2 + 1];
    const float* y0 = g_y + (size_t)e0 * D_DIM;
    const float* y1 = g_y + (size_t)e1 * D_DIM;
    float* o = out + (size_t)t * D_DIM;
    for (int d = threadIdx.x; d < D_DIM; d += blockDim.x)
        o[d] = w0 * y0[d] + w1 * y1[d];
}

extern "C" void kernel_launch(void* const* d_in, const int* in_sizes, int n_in,
                              void* d_out, int out_size) {
    const float* x  = (const float*)d_in[0];
    const float* gw = (const float*)d_in[1];
    const float* w1 = (const float*)d_in[2];
    const float* b1 = (const float*)d_in[3];
    const float* w2 = (const float*)d_in[4];
    const float* b2 = (const float*)d_in[5];
    float* out = (float*)d_out;

    static int configured = 0;
    if (!configured) {
        cudaFuncSetAttribute(ffn1_mma, cudaFuncAttributeMaxDynamicSharedMemorySize, SMEM_BYTES);
        cudaFuncSetAttribute(ffn2_mma, cudaFuncAttributeMaxDynamicSharedMemorySize, SMEM_BYTES);
        configured = 1;
    }

    __nv_bfloat16 *xh, *xl, *w1h, *w1l, *w2h, *w2l;
    cudaGetSymbolAddress((void**)&xh,  g_xh);
    cudaGetSymbolAddress((void**)&xl,  g_xl);
    cudaGetSymbolAddress((void**)&w1h, g_w1h);
    cudaGetSymbolAddress((void**)&w1l, g_w1l);
    cudaGetSymbolAddress((void**)&w2h, g_w2h);
    cudaGetSymbolAddress((void**)&w2l, g_w2l);

    zero_cnt_kernel<<<1, 32>>>();
    gate_kernel<<<T_TOK, 256>>>(x, gw);
    split_kernel<<<4096, 256>>>(x,  xh,  xl,  (T_TOK * D_DIM) / 4);
    split_kernel<<<8192, 256>>>(w1, w1h, w1l, (E_NUM * F2 * D_DIM) / 4);
    split_kernel<<<8192, 256>>>(w2, w2h, w2l, (E_NUM * D_DIM * F_DIM) / 4);
    ffn1_mma<<<dim3(F2 / BN, CAP / BM, E_NUM), 256, SMEM_BYTES>>>(b1);
    ffn2_mma<<<dim3(D_DIM / BN, CAP / BM, E_NUM), 256, SMEM_BYTES>>>(b2);
    combine_kernel<<<T_TOK, 256>>>(out);
}

// round 8
// speedup vs baseline: 6.5024x; 2.2689x over previous
#include <cuda_runtime.h>
#include <cuda_fp16.h>
#include <math.h>
#include <stdint.h>

// Problem constants
#define T_TOK 4096
#define D_DIM 1024
#define E_NUM 8
#define F_DIM 2048
#define F2    4096
#define CAP   4096

// Tile config: 128x128 CTA tile, BK=64 fp16 (128B rows, SW128), 3 stages
#define BM 128
#define BN 128
#define BK 64
#define MAT   16384                   // one matrix tile: 128 rows x 128B
#define STAGE (2 * MAT)               // A + B = 32768
#define NSTAGE 3
#define SMEM_BYTES (NSTAGE * STAGE)   // 98304

// ---------------- scratch (device globals; no allocs allowed) ----------------
__device__ int   g_cnt[E_NUM];
__device__ int   g_tok[E_NUM * CAP];
__device__ int   g_t2e[T_TOK * 2];
__device__ float g_t2w[T_TOK * 2];
__device__ __half g_H[(size_t)E_NUM * CAP * F_DIM];     // 134 MB
__device__ float  g_y[(size_t)E_NUM * CAP * D_DIM];     // 134 MB
// fp16 copies of operands
__device__ __half g_x16[(size_t)T_TOK * D_DIM];         // 8 MB
__device__ __half g_w116[(size_t)E_NUM * F2 * D_DIM];   // 67 MB
__device__ __half g_w216[(size_t)E_NUM * D_DIM * F_DIM];// 33.5 MB

// ---------------- helpers ----------------
__device__ __forceinline__ uint32_t smem_u32(const void* p) {
    uint32_t a;
    asm("{ .reg .u64 t; cvta.to.shared.u64 t, %1; cvt.u32.u64 %0, t; }" : "=r"(a) : "l"(p));
    return a;
}
__device__ __forceinline__ void ldsm_x4(uint32_t& r0, uint32_t& r1, uint32_t& r2, uint32_t& r3,
                                        uint32_t addr) {
    asm volatile("ldmatrix.sync.aligned.m8n8.x4.shared.b16 {%0,%1,%2,%3}, [%4];"
                 : "=r"(r0), "=r"(r1), "=r"(r2), "=r"(r3) : "r"(addr));
}
__device__ __forceinline__ void mma_f16(float* c,
                                        uint32_t a0, uint32_t a1, uint32_t a2, uint32_t a3,
                                        uint32_t b0, uint32_t b1) {
    asm volatile("mma.sync.aligned.m16n8k16.row.col.f32.f16.f16.f32 "
                 "{%0,%1,%2,%3}, {%4,%5,%6,%7}, {%8,%9}, {%0,%1,%2,%3};"
                 : "+f"(c[0]), "+f"(c[1]), "+f"(c[2]), "+f"(c[3])
                 : "r"(a0), "r"(a1), "r"(a2), "r"(a3), "r"(b0), "r"(b1));
}
#define CP16(dst, src) \
    asm volatile("cp.async.cg.shared.global [%0], [%1], 16;" :: "r"(dst), "l"(src) : "memory")
#define CP_COMMIT() asm volatile("cp.async.commit_group;" ::: "memory")
#define CP_WAIT2()  asm volatile("cp.async.wait_group 2;" ::: "memory")

// swizzled byte offset within a 128x128B matrix: row in [0,128), 16B chunk in [0,8)
#define SWOFF(row, ch) ((row) * 128 + (((ch) * 16) ^ (((row) & 7) << 4)))

// ---------------- kernel: fp32 -> fp16 convert (grid-stride over float4) ----------------
__global__ void cvt_kernel(const float* __restrict__ src,
                           __half* __restrict__ dst, int n4) {
    int i = blockIdx.x * blockDim.x + threadIdx.x;
    int stride = gridDim.x * blockDim.x;
    for (; i < n4; i += stride) {
        float4 v = ((const float4*)src)[i];
        __half2 p0 = __floats2half2_rn(v.x, v.y);
        __half2 p1 = __floats2half2_rn(v.z, v.w);
        *(uint2*)(dst + 4 * (size_t)i) =
            make_uint2(*(uint32_t*)&p0, *(uint32_t*)&p1);
    }
}

// ---------------- kernel 0: reset counters ----------------
__global__ void zero_cnt_kernel() {
    if (threadIdx.x < E_NUM) g_cnt[threadIdx.x] = 0;
}

// ---------------- kernel 1: gating + top-2 routing (fp32, exact) ----------------
__global__ void gate_kernel(const float* __restrict__ x,
                            const float* __restrict__ gw) {
    int t = blockIdx.x;
    __shared__ float xs[D_DIM];
    __shared__ float gates[E_NUM];
    int tid = threadIdx.x;
    for (int i = tid; i < D_DIM; i += blockDim.x)
        xs[i] = x[(size_t)t * D_DIM + i];
    __syncthreads();
    int wid = tid >> 5, lane = tid & 31;
    float s = 0.f;
    for (int d = lane; d < D_DIM; d += 32)
        s += xs[d] * gw[d * E_NUM + wid];
    #pragma unroll
    for (int o = 16; o > 0; o >>= 1)
        s += __shfl_down_sync(0xffffffffu, s, o);
    if (lane == 0) gates[wid] = s;
    __syncthreads();
    if (tid == 0) {
        int i0 = 0; float g0 = gates[0];
        #pragma unroll
        for (int e = 1; e < E_NUM; e++)
            if (gates[e] > g0) { g0 = gates[e]; i0 = e; }
        int i1 = -1; float g1 = -1e30f;
        #pragma unroll
        for (int e = 0; e < E_NUM; e++)
            if (e != i0 && gates[e] > g1) { g1 = gates[e]; i1 = e; }
        float ex = expf(g1 - g0);
        float w0 = 1.f / (1.f + ex);
        float w1 = ex / (1.f + ex);
        int s0 = atomicAdd(&g_cnt[i0], 1);
        int s1 = atomicAdd(&g_cnt[i1], 1);
        g_tok[i0 * CAP + s0] = t;
        g_tok[i1 * CAP + s1] = t;
        g_t2e[t * 2 + 0] = i0 * CAP + s0;
        g_t2e[t * 2 + 1] = i1 * CAP + s1;
        g_t2w[t * 2 + 0] = w0;
        g_t2w[t * 2 + 1] = w1;
    }
}

// ======================================================================
// GEMMs: 128x128x64 CTA chunk, 8 warps (4x2), warp tile 32x64,
// m16n8k16 fp16 single-term, SW128 swizzle, 3-stage cp.async, 2 CTAs/SM.
// ======================================================================

#define LDSM_OFFSETS() \
    const int lj = lane >> 3, lr = lane & 7; \
    int a_row[2], a_sw[2], b_row[4], b_sw[4]; \
    const int a_chb = (lj >> 1) * 16; \
    const int b_chb = (lj & 1) * 16; \
    _Pragma("unroll") \
    for (int mt = 0; mt < 2; mt++) { \
        int ra = warp_m * 32 + mt * 16 + (lj & 1) * 8 + lr; \
        a_row[mt] = ra * 128; a_sw[mt] = (ra & 7) << 4; \
    } \
    _Pragma("unroll") \
    for (int np = 0; np < 4; np++) { \
        int rb = warp_n * 64 + np * 16 + (lj >> 1) * 8 + lr; \
        b_row[np] = rb * 128; b_sw[np] = (rb & 7) << 4; \
    }

#define MMA_COMPUTE(base) do { \
    _Pragma("unroll") \
    for (int kk = 0; kk < 4; kk++) { \
        uint32_t af[2][4]; \
        _Pragma("unroll") \
        for (int mt = 0; mt < 2; mt++) \
            ldsm_x4(af[mt][0], af[mt][1], af[mt][2], af[mt][3], \
                    (base) + a_row[mt] + ((kk * 32 + a_chb) ^ a_sw[mt])); \
        _Pragma("unroll") \
        for (int np = 0; np < 4; np++) { \
            uint32_t bf[4]; \
            ldsm_x4(bf[0], bf[1], bf[2], bf[3], \
                    (base) + MAT + b_row[np] + ((kk * 32 + b_chb) ^ b_sw[np])); \
            _Pragma("unroll") \
            for (int mt = 0; mt < 2; mt++) { \
                mma_f16(acc[mt][2 * np],     af[mt][0], af[mt][1], af[mt][2], af[mt][3], bf[0], bf[1]); \
                mma_f16(acc[mt][2 * np + 1], af[mt][0], af[mt][1], af[mt][2], af[mt][3], bf[2], bf[3]); \
            } \
        } \
    } } while (0)

// ---------------- kernel 2: GEMM1 (h = x @ W1^T + b1) + SwiGLU -> fp16 H ----------------
__global__ void __launch_bounds__(256, 2) ffn1_mma(
    const float* __restrict__ b1) {
    extern __shared__ char smem[];
    __shared__ int stok[128];
    const int e = blockIdx.z;
    const int cnt = g_cnt[e];
    const int row0 = blockIdx.y * BM;
    if (row0 >= cnt) return;
    const int c0 = blockIdx.x * BN;

    const int tid = threadIdx.x;
    const int lane = tid & 31;
    const int warp_m = (tid >> 5) & 3;
    const int warp_n = tid >> 7;
    const uint32_t sb = smem_u32(smem);

    if (tid < 128) {
        int r = row0 + tid;
        stok[tid] = (r < cnt) ? g_tok[e * CAP + r] : g_tok[e * CAP];
    }
    __syncthreads();

    LDSM_OFFSETS();

    float acc[2][8][4];
    #pragma unroll
    for (int i = 0; i < 2; i++)
        #pragma unroll
        for (int j = 0; j < 8; j++)
            #pragma unroll
            for (int k = 0; k < 4; k++) acc[i][j][k] = 0.f;

    const int NCHUNK = D_DIM / BK;   // 16

    // per chunk: A tile 1024 x 16B (j=0..3), B tile 1024 x 16B (j=4..7)
    #define G1_ISSUE(c, buf) do { \
        int k0 = (c) * BK; \
        uint32_t st = sb + (buf) * STAGE; \
        _Pragma("unroll") \
        for (int j = 0; j < 4; j++) { \
            int idx = tid + 256 * j; \
            int row = idx >> 3, ch = idx & 7; \
            CP16(st + SWOFF(row, ch), \
                 g_x16 + (size_t)stok[row] * D_DIM + k0 + ch * 8); \
        } \
        _Pragma("unroll") \
        for (int j = 0; j < 4; j++) { \
            int idx = tid + 256 * j; \
            int row = idx >> 3, ch = idx & 7; \
            CP16(st + MAT + SWOFF(row, ch), \
                 g_w116 + ((size_t)e * F2 + c0 + row) * D_DIM + k0 + ch * 8); \
        } } while (0)

    G1_ISSUE(0, 0); CP_COMMIT();
    G1_ISSUE(1, 1); CP_COMMIT();
    G1_ISSUE(2, 2); CP_COMMIT();

    int buf = 0;
    #pragma unroll 1
    for (int c = 0; c < NCHUNK; c++) {
        CP_WAIT2();
        __syncthreads();
        MMA_COMPUTE(sb + buf * STAGE);
        __syncthreads();
        if (c + 3 < NCHUNK) G1_ISSUE(c + 3, buf);
        CP_COMMIT();
        buf = (buf == 2) ? 0 : buf + 1;
    }
    #undef G1_ISSUE

    // epilogue: bias + SwiGLU, write fp16 H
    const int rl0 = warp_m * 32 + (lane >> 2);
    const int cb0 = c0 + warp_n * 64 + (lane & 3) * 2;
    #pragma unroll
    for (int mt = 0; mt < 2; mt++) {
        #pragma unroll
        for (int dd = 0; dd < 2; dd++) {
            int lrow = rl0 + mt * 16 + dd * 8;
            if (row0 + lrow >= cnt) continue;
            size_t hb = ((size_t)e * CAP + row0 + lrow) * F_DIM;
            #pragma unroll
            for (int nt = 0; nt < 8; nt++) {
                int colp = cb0 + nt * 8;
                float g = acc[mt][nt][dd * 2]     + b1[e * F2 + colp];
                float v = acc[mt][nt][dd * 2 + 1] + b1[e * F2 + colp + 1];
                g = fminf(g, 9.0f);
                v = fmaxf(fminf(v, 9.0f), -9.0f);
                float sig = 1.0f / (1.0f + __expf(-1.702f * g));
                float h = g * sig * (v + 1.0f);
                g_H[hb + (colp >> 1)] = __float2half_rn(h);
            }
        }
    }
}

// ---------------- kernel 3: GEMM2 (y = H @ W2^T + b2) ----------------
__global__ void __launch_bounds__(256, 2) ffn2_mma(
    const float* __restrict__ b2) {
    extern __shared__ char smem[];
    const int e = blockIdx.z;
    const int cnt = g_cnt[e];
    const int row0 = blockIdx.y * BM;
    if (row0 >= cnt) return;
    const int d0 = blockIdx.x * BN;

    const int tid = threadIdx.x;
    const int lane = tid & 31;
    const int warp_m = (tid >> 5) & 3;
    const int warp_n = tid >> 7;
    const uint32_t sb = smem_u32(smem);

    LDSM_OFFSETS();

    float acc[2][8][4];
    #pragma unroll
    for (int i = 0; i < 2; i++)
        #pragma unroll
        for (int j = 0; j < 8; j++)
            #pragma unroll
            for (int k = 0; k < 4; k++) acc[i][j][k] = 0.f;

    const int NCHUNK = F_DIM / BK;   // 32

    #define G2_ISSUE(c, buf) do { \
        int k0 = (c) * BK; \
        uint32_t st = sb + (buf) * STAGE; \
        _Pragma("unroll") \
        for (int j = 0; j < 4; j++) { \
            int idx = tid + 256 * j; \
            int row = idx >> 3, ch = idx & 7; \
            CP16(st + SWOFF(row, ch), \
                 g_H + ((size_t)e * CAP + row0 + row) * F_DIM + k0 + ch * 8); \
        } \
        _Pragma("unroll") \
        for (int j = 0; j < 4; j++) { \
            int idx = tid + 256 * j; \
            int row = idx >> 3, ch = idx & 7; \
            CP16(st + MAT + SWOFF(row, ch), \
                 g_w216 + ((size_t)e * D_DIM + d0 + row) * F_DIM + k0 + ch * 8); \
        } } while (0)

    G2_ISSUE(0, 0); CP_COMMIT();
    G2_ISSUE(1, 1); CP_COMMIT();
    G2_ISSUE(2, 2); CP_COMMIT();

    int buf = 0;
    #pragma unroll 1
    for (int c = 0; c < NCHUNK; c++) {
        CP_WAIT2();
        __syncthreads();
        MMA_COMPUTE(sb + buf * STAGE);
        __syncthreads();
        if (c + 3 < NCHUNK) G2_ISSUE(c + 3, buf);
        CP_COMMIT();
        buf = (buf == 2) ? 0 : buf + 1;
    }
    #undef G2_ISSUE

    // epilogue: bias + store fp32 y
    const int rl0 = warp_m * 32 + (lane >> 2);
    const int cb0 = d0 + warp_n * 64 + (lane & 3) * 2;
    #pragma unroll
    for (int mt = 0; mt < 2; mt++) {
        #pragma unroll
        for (int dd = 0; dd < 2; dd++) {
            int lrow = rl0 + mt * 16 + dd * 8;
            if (row0 + lrow >= cnt) continue;
            float* yrow = g_y + ((size_t)e * CAP + row0 + lrow) * D_DIM;
            #pragma unroll
            for (int nt = 0; nt < 8; nt++) {
                int col = cb0 + nt * 8;
                float2 o;
                o.x = acc[mt][nt][dd * 2]     + b2[e * D_DIM + col];
                o.y = acc[mt][nt][dd * 2 + 1] + b2[e * D_DIM + col + 1];
                *(float2*)(yrow + col) = o;
            }
        }
    }
}

// ---------------- kernel 4: deterministic weighted combine ----------------
__global__ void combine_kernel(float* __restrict__ out) {
    int t = blockIdx.x;
    int   e0 = g_t2e[t * 2 + 0], e1 = g_t2e[t * 2 + 1];
    float w0 = g_t2w[t * 2 + 0], w1 = g_t2w[t * 2 + 1];
    const float* y0 = g_y + (size_t)e0 * D_DIM;
    const float* y1 = g_y + (size_t)e1 * D_DIM;
    float* o = out + (size_t)t * D_DIM;
    for (int d = threadIdx.x; d < D_DIM; d += blockDim.x)
        o[d] = w0 * y0[d] + w1 * y1[d];
}

extern "C" void kernel_launch(void* const* d_in, const int* in_sizes, int n_in,
                              void* d_out, int out_size) {
    const float* x  = (const float*)d_in[0];
    const float* gw = (const float*)d_in[1];
    const float* w1 = (const float*)d_in[2];
    const float* b1 = (const float*)d_in[3];
    const float* w2 = (const float*)d_in[4];
    const float* b2 = (const float*)d_in[5];
    float* out = (float*)d_out;

    static int configured = 0;
    if (!configured) {
        cudaFuncSetAttribute(ffn1_mma, cudaFuncAttributeMaxDynamicSharedMemorySize, SMEM_BYTES);
        cudaFuncSetAttribute(ffn2_mma, cudaFuncAttributeMaxDynamicSharedMemorySize, SMEM_BYTES);
        configured = 1;
    }

    __half *x16, *w116, *w216;
    cudaGetSymbolAddress((void**)&x16,  g_x16);
    cudaGetSymbolAddress((void**)&w116, g_w116);
    cudaGetSymbolAddress((void**)&w216, g_w216);

    zero_cnt_kernel<<<1, 32>>>();
    gate_kernel<<<T_TOK, 256>>>(x, gw);
    cvt_kernel<<<2048, 256>>>(x,  x16,  (T_TOK * D_DIM) / 4);
    cvt_kernel<<<8192, 256>>>(w1, w116, (E_NUM * F2 * D_DIM) / 4);
    cvt_kernel<<<8192, 256>>>(w2, w216, (E_NUM * D_DIM * F_DIM) / 4);
    ffn1_mma<<<dim3(F2 / BN, CAP / BM, E_NUM), 256, SMEM_BYTES>>>(b1);
    ffn2_mma<<<dim3(D_DIM / BN, CAP / BM, E_NUM), 256, SMEM_BYTES>>>(b2);
    combine_kernel<<<T_TOK, 256>>>(out);
}